// round 5
// baseline (speedup 1.0000x reference)
#include <cuda_runtime.h>
#include <cuda_bf16.h>
#include <math.h>
#include <stdint.h>

// Problem constants
#define NN   4096
#define BB   4
#define DD   4
#define TT   5
#define F1C  32
#define F2C  64
#define CF   256            // BB * F2C columns of cond matrix
#define NSEG (NN / 32)      // 128 u32 words per packed row

// GEMM tiling
#define MT   64
#define NT   64
#define KT   64
#define NKT  (NN / KT)      // 64
#define LDSB 144            // padded smem row stride bytes
#define BTILE (NT * LDSB)   // 9216
#define ATILE (MT * LDSB)   // 9216
#define GEMM_SMEM 75776     // max(mainloop 46080, epilogue 75520)

// Scratch (device globals — no allocation allowed)
__device__ float          g_cond[NN * CF];        // cond fp32 [n][b*64+f]
__device__ __nv_bfloat16  g_condT[CF * NN];       // cond bf16 transposed [c][n]
__device__ unsigned       g_Abits[NN * NSEG];     // bit-packed adjacency (2 MB)
__device__ float          g_invdeg[NN];
__device__ unsigned       g_colOr[NSEG];          // column-nonzero bitmask

// ---------------------------------------------------------------------------
// helpers
// ---------------------------------------------------------------------------
__device__ __forceinline__ void cp_async16(void* smem_dst, const void* gmem_src) {
    unsigned saddr = (unsigned)__cvta_generic_to_shared(smem_dst);
    asm volatile("cp.async.cg.shared.global [%0], [%1], 16;\n"
                 :: "r"(saddr), "l"(gmem_src) : "memory");
}
__device__ __forceinline__ void cp_async_commit() {
    asm volatile("cp.async.commit_group;\n" ::: "memory");
}
template <int N>
__device__ __forceinline__ void cp_async_wait() {
    asm volatile("cp.async.wait_group %0;\n" :: "n"(N) : "memory");
}
__device__ __forceinline__ void ldsm_x4(uint32_t &r0, uint32_t &r1,
                                        uint32_t &r2, uint32_t &r3,
                                        uint32_t saddr) {
    asm volatile("ldmatrix.sync.aligned.m8n8.x4.shared.b16 {%0,%1,%2,%3}, [%4];\n"
                 : "=r"(r0), "=r"(r1), "=r"(r2), "=r"(r3) : "r"(saddr));
}
__device__ __forceinline__ void mma_bf16(float c[4],
    uint32_t a0, uint32_t a1, uint32_t a2, uint32_t a3,
    uint32_t b0, uint32_t b1)
{
    asm volatile(
        "mma.sync.aligned.m16n8k16.row.col.f32.bf16.bf16.f32 "
        "{%0,%1,%2,%3}, {%4,%5,%6,%7}, {%8,%9}, {%0,%1,%2,%3};\n"
        : "+f"(c[0]), "+f"(c[1]), "+f"(c[2]), "+f"(c[3])
        : "r"(a0), "r"(a1), "r"(a2), "r"(a3), "r"(b0), "r"(b1));
}

// ---------------------------------------------------------------------------
// Kernel 1: prep — bit-pack edges, row invdeg, column-OR (alive).
// grid 512 x 256; warp per row.
// ---------------------------------------------------------------------------
__global__ __launch_bounds__(256) void prep_kernel(const int* __restrict__ edges)
{
    __shared__ unsigned sOr[NSEG];
    const int tid  = threadIdx.x;
    const int wid  = tid >> 5;
    const int lane = tid & 31;
    for (int i = tid; i < NSEG; i += 256) sOr[i] = 0u;
    __syncthreads();

    const int j = blockIdx.x * 8 + wid;
    const int* row = edges + (size_t)j * NN;
    int deg = 0;
    #pragma unroll 1
    for (int s4 = 0; s4 < NSEG; s4 += 4) {
        int e0 = row[(s4 + 0) * 32 + lane];
        int e1 = row[(s4 + 1) * 32 + lane];
        int e2 = row[(s4 + 2) * 32 + lane];
        int e3 = row[(s4 + 3) * 32 + lane];
        unsigned m0 = __ballot_sync(0xffffffffu, e0 != 0);
        unsigned m1 = __ballot_sync(0xffffffffu, e1 != 0);
        unsigned m2 = __ballot_sync(0xffffffffu, e2 != 0);
        unsigned m3 = __ballot_sync(0xffffffffu, e3 != 0);
        if (lane == 0) {
            g_Abits[j * NSEG + s4 + 0] = m0;
            g_Abits[j * NSEG + s4 + 1] = m1;
            g_Abits[j * NSEG + s4 + 2] = m2;
            g_Abits[j * NSEG + s4 + 3] = m3;
            deg += __popc(m0) + __popc(m1) + __popc(m2) + __popc(m3);
            if (m0) atomicOr(&sOr[s4 + 0], m0);
            if (m1) atomicOr(&sOr[s4 + 1], m1);
            if (m2) atomicOr(&sOr[s4 + 2], m2);
            if (m3) atomicOr(&sOr[s4 + 3], m3);
        }
    }
    if (lane == 0) g_invdeg[j] = 1.0f / fmaxf((float)deg, 1.0f);
    __syncthreads();
    for (int i = tid; i < NSEG; i += 256)
        if (sOr[i]) atomicOr(&g_colOr[i], sOr[i]);
}

// ---------------------------------------------------------------------------
// Kernel 2: temporal conv -> g_cond fp32 + g_condT bf16 (transposed)
// grid 512 x 256; CTA = 8 n-values x 4 batches = 32 items, 4 per warp.
// W2 stored transposed [p][f][c-padded36] for float4 LDS.
// ---------------------------------------------------------------------------
__global__ __launch_bounds__(256) void cond_kernel(
    const float* __restrict__ ts,
    const float* __restrict__ Wc1, const float* __restrict__ bc1,
    const float* __restrict__ Wc2, const float* __restrict__ bc2)
{
    __shared__ float sW1[3 * DD * F1C];
    __shared__ float sW2t[3 * 64 * 36];    // [p][f][c], c-stride 36
    __shared__ float sb1[F1C];
    __shared__ float sb2[F2C];
    __shared__ float sx[8][20];
    __shared__ float sh[8][96];
    __shared__ __nv_bfloat16 scT[CF][8];

    const int tid  = threadIdx.x;
    const int wid  = tid >> 5;
    const int lane = tid & 31;
    const int n0   = blockIdx.x * 8;

    for (int i = tid; i < 3 * 64 * 32; i += 256) {
        int p = i >> 11, rem = i & 2047, f = rem >> 5, c = rem & 31;
        sW2t[(p * 64 + f) * 36 + c] = Wc2[(p * F1C + c) * F2C + f];
    }
    for (int i = tid; i < 3 * DD * F1C; i += 256) sW1[i] = Wc1[i];
    if (tid < F1C) sb1[tid] = bc1[tid];
    if (tid < F2C) sb2[tid] = bc2[tid];
    __syncthreads();

    for (int it = 0; it < 4; it++) {
        const int item = wid * 4 + it;     // 0..31
        const int b    = item >> 3;
        const int nloc = item & 7;
        const int n    = n0 + nloc;

        if (lane < TT * DD) {
            int t = lane >> 2, d = lane & 3;
            sx[wid][lane] = ts[((size_t)(b * TT + t) * NN + n) * DD + d];
        }
        __syncwarp();

        #pragma unroll
        for (int p = 0; p < 3; p++) {
            float s = sb1[lane];
            #pragma unroll
            for (int r = 0; r < 3; r++)
                #pragma unroll
                for (int d = 0; d < DD; d++)
                    s += sx[wid][(p + r) * DD + d] * sW1[(r * DD + d) * F1C + lane];
            sh[wid][p * 32 + lane] = fmaxf(s, 0.f);
        }
        __syncwarp();

        float s0 = sb2[lane], s1 = sb2[lane + 32];
        #pragma unroll
        for (int p = 0; p < 3; p++) {
            const float4* h4 = (const float4*)&sh[wid][p * 32];
            const float4* wa = (const float4*)&sW2t[(p * 64 + lane) * 36];
            const float4* wb = (const float4*)&sW2t[(p * 64 + lane + 32) * 36];
            #pragma unroll
            for (int q = 0; q < 8; q++) {
                float4 h = h4[q], a = wa[q], bq = wb[q];
                s0 += h.x * a.x + h.y * a.y + h.z * a.z + h.w * a.w;
                s1 += h.x * bq.x + h.y * bq.y + h.z * bq.z + h.w * bq.w;
            }
        }
        const int cc0 = b * F2C + lane;
        g_cond[(size_t)n * CF + cc0]      = s0;
        g_cond[(size_t)n * CF + cc0 + 32] = s1;
        scT[cc0][nloc]      = __float2bfloat16(s0);
        scT[cc0 + 32][nloc] = __float2bfloat16(s1);
        __syncwarp();
    }
    __syncthreads();

    // coalesced-ish condT store: 256 rows x 16 bytes
    if (tid < CF)
        *(int4*)&g_condT[(size_t)tid * NN + n0] = *(int4*)&scT[tid][0];
}

// ---------------------------------------------------------------------------
// Kernel 3: fused S = A @ cond (bf16 mma.sync) + epilogue.
// grid (4 batches, 64 row-groups) x 256 threads. CTA: 64 rows x 64 cols.
// A expanded from g_Abits; B 3-stage cp.async; ldmatrix fragment loads.
// ---------------------------------------------------------------------------
__global__ __launch_bounds__(256, 2) void gemm_kernel(
    const float* __restrict__ ts,
    const float* __restrict__ Wg1, const float* __restrict__ bg,
    const float* __restrict__ Wd,  const float* __restrict__ bd,
    const float* __restrict__ Wo,  const float* __restrict__ bo,
    float* __restrict__ out)
{
    extern __shared__ char smem[];
    const unsigned smem_u = (unsigned)__cvta_generic_to_shared(smem);
    // layout: B0,B1,B2 (3*BTILE), A0,A1 (2*ATILE)
    char* Bbuf0 = smem;
    char* Abuf0 = smem + 3 * BTILE;

    const int tid  = threadIdx.x;
    const int wid  = tid >> 5;
    const int lane = tid & 31;
    const int g    = lane >> 2;
    const int t    = lane & 3;
    const int mi   = wid >> 1;            // 0..3 m16 block
    const int nq   = wid & 1;             // 0..1 n32 block
    const int c0   = blockIdx.x * NT;     // batch * 64
    const int j0   = blockIdx.y * MT;

    // ldmatrix lane offsets
    const int aoff = (mi * 16 + ((lane >> 3) & 1) * 8 + (lane & 7)) * LDSB
                   + (lane >> 4) * 16;
    const int boff = (nq * 32 + (lane >> 4) * 8 + (lane & 7)) * LDSB
                   + ((lane >> 3) & 1) * 16;

    // A expansion mapping: 4 threads per row, 16 cols each
    const int arow = tid >> 2;            // 0..63
    const int tq   = tid & 3;
    const unsigned* abit_row = g_Abits + (size_t)(j0 + arow) * NSEG + (tq >> 1);
    const int ash = (tq & 1) * 16;
    const int astore = arow * LDSB + tq * 32;

    float acc[4][4] = {};

    // ---- prologue: B tiles 0,1 + A tile 0 ----
    #pragma unroll
    for (int s = 0; s < 2; s++) {
        char* Bn = Bbuf0 + s * BTILE;
        for (int ch = tid; ch < NT * 8; ch += 256) {
            int rw = ch >> 3, off = ch & 7;
            cp_async16(Bn + rw * LDSB + off * 16,
                       g_condT + (size_t)(c0 + rw) * NN + s * KT + off * 8);
        }
        cp_async_commit();
    }
    {
        unsigned w = abit_row[0] >> ash;
        uint32_t p[8];
        #pragma unroll
        for (int i = 0; i < 8; i++)
            p[i] = ((w >> (2 * i)) & 1u ? 0x3F80u : 0u)
                 | ((w >> (2 * i + 1)) & 1u ? 0x3F800000u : 0u);
        *(uint4*)(Abuf0 + astore)      = make_uint4(p[0], p[1], p[2], p[3]);
        *(uint4*)(Abuf0 + astore + 16) = make_uint4(p[4], p[5], p[6], p[7]);
    }
    cp_async_wait<1>();
    __syncthreads();

    // ---- mainloop ----
    #pragma unroll 1
    for (int kt = 0; kt < NKT; kt++) {
        const unsigned Au = smem_u + 3 * BTILE + (kt & 1) * ATILE;
        const unsigned Bu = smem_u + (kt % 3) * BTILE;

        unsigned wnext = 0;
        const bool pf = (kt + 1 < NKT);
        if (pf) wnext = abit_row[(kt + 1) * 2] >> ash;

        if (kt + 2 < NKT) {
            char* Bn = Bbuf0 + ((kt + 2) % 3) * BTILE;
            const int kp = (kt + 2) * KT;
            for (int ch = tid; ch < NT * 8; ch += 256) {
                int rw = ch >> 3, off = ch & 7;
                cp_async16(Bn + rw * LDSB + off * 16,
                           g_condT + (size_t)(c0 + rw) * NN + kp + off * 8);
            }
            cp_async_commit();
        }

        #pragma unroll
        for (int kk = 0; kk < 4; kk++) {
            uint32_t a0, a1, a2, a3, r0, r1, r2, r3, q0, q1, q2, q3;
            ldsm_x4(a0, a1, a2, a3, Au + aoff + kk * 32);
            ldsm_x4(r0, r1, r2, r3, Bu + boff + kk * 32);
            ldsm_x4(q0, q1, q2, q3, Bu + boff + 16 * LDSB + kk * 32);
            mma_bf16(acc[0], a0, a1, a2, a3, r0, r1);
            mma_bf16(acc[1], a0, a1, a2, a3, r2, r3);
            mma_bf16(acc[2], a0, a1, a2, a3, q0, q1);
            mma_bf16(acc[3], a0, a1, a2, a3, q2, q3);
        }

        if (pf) {
            char* An = Abuf0 + ((kt + 1) & 1) * ATILE;
            uint32_t p[8];
            #pragma unroll
            for (int i = 0; i < 8; i++)
                p[i] = ((wnext >> (2 * i)) & 1u ? 0x3F80u : 0u)
                     | ((wnext >> (2 * i + 1)) & 1u ? 0x3F800000u : 0u);
            *(uint4*)(An + astore)      = make_uint4(p[0], p[1], p[2], p[3]);
            *(uint4*)(An + astore + 16) = make_uint4(p[4], p[5], p[6], p[7]);
        }
        if (kt + 2 < NKT) cp_async_wait<1>(); else cp_async_wait<0>();
        __syncthreads();
    }

    // ---- epilogue overlay ----
    float* sf   = (float*)smem;
    float* sS   = sf;               // 4096  (64 x 64)
    float* sWg1 = sf + 4096;        // 4096
    float* sWd  = sf + 8192;        // 8192
    float* sWo  = sf + 16384;       // 256
    float* sbg  = sf + 16640;       // 64
    float* sbd  = sf + 16704;       // 64
    float* sbo  = sf + 16768;       // 64 (4 used)
    float* swk  = sf + 16832;       // 8 warps x 256

    #pragma unroll
    for (int ni = 0; ni < 4; ni++) {
        const int row = mi * 16 + g;
        const int col = nq * 32 + ni * 8 + 2 * t;
        sS[row * 64 + col]           = acc[ni][0];
        sS[row * 64 + col + 1]       = acc[ni][1];
        sS[(row + 8) * 64 + col]     = acc[ni][2];
        sS[(row + 8) * 64 + col + 1] = acc[ni][3];
    }
    for (int i = tid; i < 4096; i += 256) sWg1[i] = Wg1[i];
    for (int i = tid; i < 8192; i += 256) sWd[i]  = Wd[i];
    if (tid < 256) sWo[tid] = Wo[tid];
    if (tid < 64) { sbg[tid] = bg[tid]; sbd[tid] = bd[tid]; }
    if (tid < 4)  sbo[tid] = bo[tid];
    __syncthreads();

    // per-warp GEMV chain: 64 rows, 8 per warp; batch = blockIdx.x
    float* agg = swk + wid * 256;
    float* cnd = agg + 64;
    float* Gv  = agg + 128;
    float* Hv  = agg + 192;
    const int b = blockIdx.x;

    for (int it = 0; it < 8; it++) {
        const int jl = wid * 8 + it;
        const int j  = j0 + jl;
        const float invd = g_invdeg[j];
        const unsigned dw = g_Abits[(size_t)j * NSEG + (j >> 5)];
        const float e  = ((dw >> (j & 31)) & 1u) ? 1.f : 0.f;
        const unsigned aw = g_colOr[j >> 5];
        const float al = ((aw >> (j & 31)) & 1u) ? 1.f : 0.f;

        #pragma unroll
        for (int u = 0; u < 2; u++) {
            const int i = lane + u * 32;
            const float cv = g_cond[(size_t)j * CF + c0 + i];
            cnd[i] = cv;
            agg[i] = (sS[jl * 64 + i] - e * cv) * invd;
        }
        __syncwarp();

        #pragma unroll
        for (int u = 0; u < 2; u++) {
            const int f = lane + u * 32;
            float gv = sbg[f];
            #pragma unroll
            for (int i = 0; i < 64; i++) gv += agg[i] * sWg1[i * 64 + f];
            Gv[f] = tanhf(gv) * al;
        }
        __syncwarp();

        #pragma unroll
        for (int u = 0; u < 2; u++) {
            const int f = lane + u * 32;
            float h = sbd[f];
            #pragma unroll
            for (int i = 0; i < 64; i++) h += cnd[i] * sWd[i * 64 + f];
            #pragma unroll
            for (int i = 0; i < 64; i++) h += Gv[i] * sWd[(64 + i) * 64 + f];
            Hv[f] = fmaxf(h, 0.f);
        }
        __syncwarp();

        if (lane < 4) {
            float o = sbo[lane];
            #pragma unroll
            for (int i = 0; i < 64; i++) o += Hv[i] * sWo[i * DD + lane];
            const float last = ts[((size_t)(b * TT + 4) * NN + j) * DD + lane];
            out[((size_t)b * NN + j) * DD + lane] = last + tanhf(o);
        }
        __syncwarp();
    }
}

// ---------------------------------------------------------------------------
// Inputs (metadata order): time_segs, edges, Wc1, bc1, Wc2, bc2,
//                          Wg1, bg, Wd, bd, Wo, bo
// ---------------------------------------------------------------------------
extern "C" void kernel_launch(void* const* d_in, const int* in_sizes, int n_in,
                              void* d_out, int out_size)
{
    const float* ts   = (const float*)d_in[0];
    const int*   edges= (const int*)  d_in[1];
    const float* Wc1  = (const float*)d_in[2];
    const float* bc1  = (const float*)d_in[3];
    const float* Wc2  = (const float*)d_in[4];
    const float* bc2  = (const float*)d_in[5];
    const float* Wg1  = (const float*)d_in[6];
    const float* bg   = (const float*)d_in[7];
    const float* Wd   = (const float*)d_in[8];
    const float* bd   = (const float*)d_in[9];
    const float* Wo   = (const float*)d_in[10];
    const float* bo   = (const float*)d_in[11];
    float* out = (float*)d_out;

    static bool attr_done = false;
    if (!attr_done) {
        cudaFuncSetAttribute(gemm_kernel,
                             cudaFuncAttributeMaxDynamicSharedMemorySize, GEMM_SMEM);
        attr_done = true;
    }

    prep_kernel<<<NN / 8, 256>>>(edges);
    cond_kernel<<<NN / 8, 256>>>(ts, Wc1, bc1, Wc2, bc2);
    gemm_kernel<<<dim3(BB, NN / MT), 256, GEMM_SMEM>>>(ts, Wg1, bg, Wd, bd,
                                                       Wo, bo, out);
}

// round 7
// speedup vs baseline: 1.3881x; 1.3881x over previous
#include <cuda_runtime.h>
#include <cuda_bf16.h>
#include <math.h>
#include <stdint.h>

// Problem constants
#define NN   4096
#define BB   4
#define DD   4
#define TT   5
#define F1C  32
#define F2C  64
#define CF   256            // BB * F2C columns of cond matrix
#define NSEG (NN / 32)      // 128 u32 words per packed row

// GEMM tiling
#define MT   64
#define NT   64
#define KT   64
#define NKT  (NN / KT)      // 64
#define LDSB 144            // padded smem row stride bytes
#define BTILE (NT * LDSB)   // 9216
#define ATILE (MT * LDSB)   // 9216
#define GEMM_SMEM 68096     // max(mainloop 46080, epilogue 17024 floats)

// Scratch (device globals — no allocation allowed)
__device__ float          g_cond[NN * CF];        // cond fp32 [n][b*64+f]
__device__ __nv_bfloat16  g_condT[CF * NN];       // cond bf16 transposed [c][n]
__device__ unsigned       g_Abits[NN * NSEG];     // bit-packed adjacency (2 MB)
__device__ float          g_invdeg[NN];
__device__ unsigned       g_colOr[NSEG];          // column-nonzero bitmask

// ---------------------------------------------------------------------------
// helpers
// ---------------------------------------------------------------------------
__device__ __forceinline__ void cp_async16(void* smem_dst, const void* gmem_src) {
    unsigned saddr = (unsigned)__cvta_generic_to_shared(smem_dst);
    asm volatile("cp.async.cg.shared.global [%0], [%1], 16;\n"
                 :: "r"(saddr), "l"(gmem_src) : "memory");
}
__device__ __forceinline__ void cp_async_commit() {
    asm volatile("cp.async.commit_group;\n" ::: "memory");
}
template <int N>
__device__ __forceinline__ void cp_async_wait() {
    asm volatile("cp.async.wait_group %0;\n" :: "n"(N) : "memory");
}
__device__ __forceinline__ void ldsm_x4(uint32_t &r0, uint32_t &r1,
                                        uint32_t &r2, uint32_t &r3,
                                        uint32_t saddr) {
    asm volatile("ldmatrix.sync.aligned.m8n8.x4.shared.b16 {%0,%1,%2,%3}, [%4];\n"
                 : "=r"(r0), "=r"(r1), "=r"(r2), "=r"(r3) : "r"(saddr));
}
__device__ __forceinline__ void mma_bf16_v(float c[4],
    uint32_t a0, uint32_t a1, uint32_t a2, uint32_t a3,
    uint32_t b0, uint32_t b1)
{
    asm volatile(
        "mma.sync.aligned.m16n8k16.row.col.f32.bf16.bf16.f32 "
        "{%0,%1,%2,%3}, {%4,%5,%6,%7}, {%8,%9}, {%0,%1,%2,%3};\n"
        : "+f"(c[0]), "+f"(c[1]), "+f"(c[2]), "+f"(c[3])
        : "r"(a0), "r"(a1), "r"(a2), "r"(a3), "r"(b0), "r"(b1));
}
__device__ __forceinline__ void fma2(float2 &a, const float2 &x, const float2 &y) {
    unsigned long long &ar = reinterpret_cast<unsigned long long &>(a);
    const unsigned long long &xr = reinterpret_cast<const unsigned long long &>(x);
    const unsigned long long &yr = reinterpret_cast<const unsigned long long &>(y);
    asm("fma.rn.f32x2 %0, %1, %2, %0;" : "+l"(ar) : "l"(xr), "l"(yr));
}

// ---------------------------------------------------------------------------
// Fused kernel 1: CTAs [0,512) = prep (bit-pack edges, invdeg, colOr),
//                 CTAs [512,1024) = temporal conv (cond + condT).
// ---------------------------------------------------------------------------
struct CondSmem {
    float sW1[3 * DD * F1C];       // 384
    float sW2t[3 * 64 * 36];       // 6912
    float sb1[F1C];
    float sb2[F2C];
    float sx[8][20];
    float sh[8][96];
    __nv_bfloat16 scT[CF][8];
};

__global__ __launch_bounds__(256) void fused_prep_cond(
    const int*   __restrict__ edges,
    const float* __restrict__ ts,
    const float* __restrict__ Wc1, const float* __restrict__ bc1,
    const float* __restrict__ Wc2, const float* __restrict__ bc2)
{
    __shared__ __align__(16) char pool[sizeof(CondSmem)];
    const int tid  = threadIdx.x;
    const int wid  = tid >> 5;
    const int lane = tid & 31;

    if (blockIdx.x < 512) {
        // ---------------- prep ----------------
        unsigned* sOr = (unsigned*)pool;   // 128 words
        for (int i = tid; i < NSEG; i += 256) sOr[i] = 0u;
        __syncthreads();

        const int j = blockIdx.x * 8 + wid;
        const int* row = edges + (size_t)j * NN;
        int deg = 0;
        #pragma unroll 1
        for (int s = 0; s < NSEG; s += 16) {
            int e[16];
            #pragma unroll
            for (int i = 0; i < 16; i++) e[i] = row[(s + i) * 32 + lane];
            unsigned m[16];
            #pragma unroll
            for (int i = 0; i < 16; i++)
                m[i] = __ballot_sync(0xffffffffu, e[i] != 0);
            if (lane == 0) {
                #pragma unroll
                for (int i = 0; i < 16; i++) {
                    g_Abits[(size_t)j * NSEG + s + i] = m[i];
                    deg += __popc(m[i]);
                    if (m[i]) atomicOr(&sOr[s + i], m[i]);
                }
            }
        }
        if (lane == 0) g_invdeg[j] = 1.0f / fmaxf((float)deg, 1.0f);
        __syncthreads();
        for (int i = tid; i < NSEG; i += 256)
            if (sOr[i]) atomicOr(&g_colOr[i], sOr[i]);
    } else {
        // ---------------- cond ----------------
        CondSmem* cs = (CondSmem*)pool;
        const int n0 = (blockIdx.x - 512) * 8;

        // coalesced gmem read of Wc2, scattered smem store (transposed, pad 36)
        for (int i = tid; i < 3 * F1C * F2C; i += 256) {
            int f = i & 63;
            int pc = i >> 6;          // p*32 + c
            int p = pc >> 5, c = pc & 31;
            cs->sW2t[(p * 64 + f) * 36 + c] = Wc2[i];
        }
        for (int i = tid; i < 3 * DD * F1C; i += 256) cs->sW1[i] = Wc1[i];
        if (tid < F1C) cs->sb1[tid] = bc1[tid];
        if (tid < F2C) cs->sb2[tid] = bc2[tid];
        __syncthreads();

        for (int it = 0; it < 4; it++) {
            const int item = wid * 4 + it;     // 0..31
            const int b    = item >> 3;
            const int nloc = item & 7;
            const int n    = n0 + nloc;

            if (lane < TT * DD) {
                int t = lane >> 2, d = lane & 3;
                cs->sx[wid][lane] = ts[((size_t)(b * TT + t) * NN + n) * DD + d];
            }
            __syncwarp();

            #pragma unroll
            for (int p = 0; p < 3; p++) {
                float s = cs->sb1[lane];
                #pragma unroll
                for (int r = 0; r < 3; r++)
                    #pragma unroll
                    for (int d = 0; d < DD; d++)
                        s += cs->sx[wid][(p + r) * DD + d]
                           * cs->sW1[(r * DD + d) * F1C + lane];
                cs->sh[wid][p * 32 + lane] = fmaxf(s, 0.f);
            }
            __syncwarp();

            float s0 = cs->sb2[lane], s1 = cs->sb2[lane + 32];
            #pragma unroll
            for (int p = 0; p < 3; p++) {
                const float4* h4 = (const float4*)&cs->sh[wid][p * 32];
                const float4* wa = (const float4*)&cs->sW2t[(p * 64 + lane) * 36];
                const float4* wb = (const float4*)&cs->sW2t[(p * 64 + lane + 32) * 36];
                #pragma unroll
                for (int q = 0; q < 8; q++) {
                    float4 h = h4[q], a = wa[q], bq = wb[q];
                    s0 += h.x * a.x + h.y * a.y + h.z * a.z + h.w * a.w;
                    s1 += h.x * bq.x + h.y * bq.y + h.z * bq.z + h.w * bq.w;
                }
            }
            const int cc0 = b * F2C + lane;
            g_cond[(size_t)n * CF + cc0]      = s0;
            g_cond[(size_t)n * CF + cc0 + 32] = s1;
            cs->scT[cc0][nloc]      = __float2bfloat16(s0);
            cs->scT[cc0 + 32][nloc] = __float2bfloat16(s1);
            __syncwarp();
        }
        __syncthreads();

        if (tid < CF)
            *(int4*)&g_condT[(size_t)tid * NN + n0] = *(int4*)&cs->scT[tid][0];
    }
}

// ---------------------------------------------------------------------------
// Kernel 2: fused S = A @ cond (bf16 mma.sync) + block-parallel epilogue.
// grid (4 batches, 64 row-groups) x 256 threads. CTA: 64 rows x 64 cols.
// ---------------------------------------------------------------------------
__global__ __launch_bounds__(256, 3) void gemm_kernel(
    const float* __restrict__ ts,
    const float* __restrict__ Wg1, const float* __restrict__ bg,
    const float* __restrict__ Wd,  const float* __restrict__ bd,
    const float* __restrict__ Wo,  const float* __restrict__ bo,
    float* __restrict__ out)
{
    extern __shared__ char smem[];
    const unsigned smem_u = (unsigned)__cvta_generic_to_shared(smem);
    char* Bbuf0 = smem;
    char* Abuf0 = smem + 3 * BTILE;

    const int tid  = threadIdx.x;
    const int wid  = tid >> 5;
    const int lane = tid & 31;
    const int g    = lane >> 2;
    const int t    = lane & 3;
    const int mi   = wid >> 1;            // 0..3 m16 block
    const int nq   = wid & 1;             // 0..1 n32 block
    const int c0   = blockIdx.x * NT;     // batch * 64
    const int j0   = blockIdx.y * MT;

    const int aoff = (mi * 16 + ((lane >> 3) & 1) * 8 + (lane & 7)) * LDSB
                   + (lane >> 4) * 16;
    const int boff = (nq * 32 + (lane >> 4) * 8 + (lane & 7)) * LDSB
                   + ((lane >> 3) & 1) * 16;

    const int arow = tid >> 2;
    const int tq   = tid & 3;
    const unsigned* abit_row = g_Abits + (size_t)(j0 + arow) * NSEG + (tq >> 1);
    const int ash = (tq & 1) * 16;
    const int astore = arow * LDSB + tq * 32;

    float acc[4][4] = {};

    // ---- prologue: B tiles 0,1 + A tile 0 ----
    #pragma unroll
    for (int s = 0; s < 2; s++) {
        char* Bn = Bbuf0 + s * BTILE;
        for (int ch = tid; ch < NT * 8; ch += 256) {
            int rw = ch >> 3, off = ch & 7;
            cp_async16(Bn + rw * LDSB + off * 16,
                       g_condT + (size_t)(c0 + rw) * NN + s * KT + off * 8);
        }
        cp_async_commit();
    }
    {
        unsigned w = abit_row[0] >> ash;
        uint32_t p[8];
        #pragma unroll
        for (int i = 0; i < 8; i++)
            p[i] = ((w >> (2 * i)) & 1u ? 0x3F80u : 0u)
                 | ((w >> (2 * i + 1)) & 1u ? 0x3F800000u : 0u);
        *(uint4*)(Abuf0 + astore)      = make_uint4(p[0], p[1], p[2], p[3]);
        *(uint4*)(Abuf0 + astore + 16) = make_uint4(p[4], p[5], p[6], p[7]);
    }
    cp_async_wait<1>();
    __syncthreads();

    // ---- mainloop ----
    #pragma unroll 1
    for (int kt = 0; kt < NKT; kt++) {
        const unsigned Au = smem_u + 3 * BTILE + (kt & 1) * ATILE;
        const unsigned Bu = smem_u + (kt % 3) * BTILE;

        unsigned wnext = 0;
        const bool pf = (kt + 1 < NKT);
        if (pf) wnext = abit_row[(kt + 1) * 2] >> ash;

        if (kt + 2 < NKT) {
            char* Bn = Bbuf0 + ((kt + 2) % 3) * BTILE;
            const int kp = (kt + 2) * KT;
            for (int ch = tid; ch < NT * 8; ch += 256) {
                int rw = ch >> 3, off = ch & 7;
                cp_async16(Bn + rw * LDSB + off * 16,
                           g_condT + (size_t)(c0 + rw) * NN + kp + off * 8);
            }
            cp_async_commit();
        }

        #pragma unroll
        for (int kk = 0; kk < 4; kk++) {
            uint32_t a0, a1, a2, a3, r0, r1, r2, r3, q0, q1, q2, q3;
            ldsm_x4(a0, a1, a2, a3, Au + aoff + kk * 32);
            ldsm_x4(r0, r1, r2, r3, Bu + boff + kk * 32);
            ldsm_x4(q0, q1, q2, q3, Bu + boff + 16 * LDSB + kk * 32);
            mma_bf16_v(acc[0], a0, a1, a2, a3, r0, r1);
            mma_bf16_v(acc[1], a0, a1, a2, a3, r2, r3);
            mma_bf16_v(acc[2], a0, a1, a2, a3, q0, q1);
            mma_bf16_v(acc[3], a0, a1, a2, a3, q2, q3);
        }

        if (pf) {
            char* An = Abuf0 + ((kt + 1) & 1) * ATILE;
            uint32_t p[8];
            #pragma unroll
            for (int i = 0; i < 8; i++)
                p[i] = ((wnext >> (2 * i)) & 1u ? 0x3F80u : 0u)
                     | ((wnext >> (2 * i + 1)) & 1u ? 0x3F800000u : 0u);
            *(uint4*)(An + astore)      = make_uint4(p[0], p[1], p[2], p[3]);
            *(uint4*)(An + astore + 16) = make_uint4(p[4], p[5], p[6], p[7]);
        }
        if (kt + 2 < NKT) cp_async_wait<1>(); else cp_async_wait<0>();
        __syncthreads();
    }

    // ---- epilogue (block-parallel, transposed staging) ----
    float* sf   = (float*)smem;
    float* aggT = sf;            // [i][r] 4096 -> later GT
    float* cndT = sf + 4096;     // [i][r] 4096 -> later HT
    float* sW   = sf + 8192;     // 8192: Wg1 (first 4096) then Wd (all)
    float* sWo  = sf + 16384;    // 256
    float* sbg  = sf + 16640;
    float* sbd  = sf + 16704;
    float* sbo  = sf + 16768;
    float* sinv = sf + 16832;
    float* sal  = sf + 16896;
    float* sdg  = sf + 16960;

    if (tid < 64) {
        const int j = j0 + tid;
        sinv[tid] = g_invdeg[j];
        unsigned dw = g_Abits[(size_t)j * NSEG + (j >> 5)];
        sdg[tid] = ((dw >> (j & 31)) & 1u) ? 1.f : 0.f;
        unsigned aw = g_colOr[j >> 5];
        sal[tid] = ((aw >> (j & 31)) & 1u) ? 1.f : 0.f;
    }
    for (int i = tid; i < 4096; i += 256) sW[i] = Wg1[i];
    if (tid < 256) sWo[tid] = Wo[tid];
    if (tid < 64) { sbg[tid] = bg[tid]; sbd[tid] = bd[tid]; }
    if (tid < 4)  sbo[tid] = bo[tid];
    __syncthreads();

    // spill acc -> aggT (with agg transform) + cndT
    {
        const int r = mi * 16 + g;
        const float i0 = sinv[r],   e0 = sdg[r];
        const float i1 = sinv[r+8], e1 = sdg[r+8];
        #pragma unroll
        for (int ni = 0; ni < 4; ni++) {
            const int col = nq * 32 + ni * 8 + 2 * t;
            float2 cv0 = *(const float2*)&g_cond[(size_t)(j0 + r)     * CF + c0 + col];
            float2 cv1 = *(const float2*)&g_cond[(size_t)(j0 + r + 8) * CF + c0 + col];
            aggT[col * 64 + r]           = (acc[ni][0] - e0 * cv0.x) * i0;
            aggT[(col + 1) * 64 + r]     = (acc[ni][1] - e0 * cv0.y) * i0;
            aggT[col * 64 + r + 8]       = (acc[ni][2] - e1 * cv1.x) * i1;
            aggT[(col + 1) * 64 + r + 8] = (acc[ni][3] - e1 * cv1.y) * i1;
            cndT[col * 64 + r]           = cv0.x;
            cndT[(col + 1) * 64 + r]     = cv0.y;
            cndT[col * 64 + r + 8]       = cv1.x;
            cndT[(col + 1) * 64 + r + 8] = cv1.y;
        }
    }
    __syncthreads();

    const int fq = tid & 15, rq = tid >> 4;
    const int f0 = fq * 4, r0 = rq * 4;

    // ---- stage 1: G = tanh(agg @ Wg1 + bg) * alive ----
    float2 ac[4][2] = {};
    #pragma unroll 4
    for (int i = 0; i < 64; i++) {
        float4 wv = *(const float4*)&sW[i * 64 + f0];
        float4 av = *(const float4*)&aggT[i * 64 + r0];
        float2 w0 = make_float2(wv.x, wv.y), w1 = make_float2(wv.z, wv.w);
        float2 d0 = make_float2(av.x, av.x);
        float2 d1 = make_float2(av.y, av.y);
        float2 d2 = make_float2(av.z, av.z);
        float2 d3 = make_float2(av.w, av.w);
        fma2(ac[0][0], d0, w0); fma2(ac[0][1], d0, w1);
        fma2(ac[1][0], d1, w0); fma2(ac[1][1], d1, w1);
        fma2(ac[2][0], d2, w0); fma2(ac[2][1], d2, w1);
        fma2(ac[3][0], d3, w0); fma2(ac[3][1], d3, w1);
    }
    float Gv[4][4];
    #pragma unroll
    for (int ri = 0; ri < 4; ri++) {
        const float al = sal[r0 + ri];
        Gv[ri][0] = tanhf(ac[ri][0].x + sbg[f0 + 0]) * al;
        Gv[ri][1] = tanhf(ac[ri][0].y + sbg[f0 + 1]) * al;
        Gv[ri][2] = tanhf(ac[ri][1].x + sbg[f0 + 2]) * al;
        Gv[ri][3] = tanhf(ac[ri][1].y + sbg[f0 + 3]) * al;
    }
    __syncthreads();
    #pragma unroll
    for (int fi = 0; fi < 4; fi++)
        *(float4*)&aggT[(f0 + fi) * 64 + r0] =
            make_float4(Gv[0][fi], Gv[1][fi], Gv[2][fi], Gv[3][fi]);
    for (int i = tid; i < 8192; i += 256) sW[i] = Wd[i];
    __syncthreads();

    // ---- stage 2: H = relu([cond, G] @ Wd + bd) ----
    float2 hc[4][2] = {};
    #pragma unroll 4
    for (int i = 0; i < 64; i++) {
        float4 wv = *(const float4*)&sW[i * 64 + f0];
        float4 cv = *(const float4*)&cndT[i * 64 + r0];
        float2 w0 = make_float2(wv.x, wv.y), w1 = make_float2(wv.z, wv.w);
        float2 d0 = make_float2(cv.x, cv.x);
        float2 d1 = make_float2(cv.y, cv.y);
        float2 d2 = make_float2(cv.z, cv.z);
        float2 d3 = make_float2(cv.w, cv.w);
        fma2(hc[0][0], d0, w0); fma2(hc[0][1], d0, w1);
        fma2(hc[1][0], d1, w0); fma2(hc[1][1], d1, w1);
        fma2(hc[2][0], d2, w0); fma2(hc[2][1], d2, w1);
        fma2(hc[3][0], d3, w0); fma2(hc[3][1], d3, w1);
    }
    #pragma unroll 4
    for (int i = 0; i < 64; i++) {
        float4 wv = *(const float4*)&sW[(64 + i) * 64 + f0];
        float4 gv = *(const float4*)&aggT[i * 64 + r0];
        float2 w0 = make_float2(wv.x, wv.y), w1 = make_float2(wv.z, wv.w);
        float2 d0 = make_float2(gv.x, gv.x);
        float2 d1 = make_float2(gv.y, gv.y);
        float2 d2 = make_float2(gv.z, gv.z);
        float2 d3 = make_float2(gv.w, gv.w);
        fma2(hc[0][0], d0, w0); fma2(hc[0][1], d0, w1);
        fma2(hc[1][0], d1, w0); fma2(hc[1][1], d1, w1);
        fma2(hc[2][0], d2, w0); fma2(hc[2][1], d2, w1);
        fma2(hc[3][0], d3, w0); fma2(hc[3][1], d3, w1);
    }
    float Hv[4][4];
    #pragma unroll
    for (int ri = 0; ri < 4; ri++) {
        Hv[ri][0] = fmaxf(hc[ri][0].x + sbd[f0 + 0], 0.f);
        Hv[ri][1] = fmaxf(hc[ri][0].y + sbd[f0 + 1], 0.f);
        Hv[ri][2] = fmaxf(hc[ri][1].x + sbd[f0 + 2], 0.f);
        Hv[ri][3] = fmaxf(hc[ri][1].y + sbd[f0 + 3], 0.f);
    }
    __syncthreads();
    #pragma unroll
    for (int fi = 0; fi < 4; fi++)
        *(float4*)&cndT[(f0 + fi) * 64 + r0] =
            make_float4(Hv[0][fi], Hv[1][fi], Hv[2][fi], Hv[3][fi]);
    __syncthreads();

    // ---- stage 3: out = last + tanh(H @ Wo + bo) ----
    {
        const int r = tid >> 2, d = tid & 3;
        const int j = j0 + r;
        const int b = blockIdx.x;
        float o = sbo[d];
        #pragma unroll
        for (int f = 0; f < 64; f++) o += cndT[f * 64 + r] * sWo[f * DD + d];
        const float last = ts[((size_t)(b * TT + 4) * NN + j) * DD + d];
        out[((size_t)b * NN + j) * DD + d] = last + tanhf(o);
    }
}

// ---------------------------------------------------------------------------
// Inputs (metadata order): time_segs, edges, Wc1, bc1, Wc2, bc2,
//                          Wg1, bg, Wd, bd, Wo, bo
// ---------------------------------------------------------------------------
extern "C" void kernel_launch(void* const* d_in, const int* in_sizes, int n_in,
                              void* d_out, int out_size)
{
    const float* ts   = (const float*)d_in[0];
    const int*   edges= (const int*)  d_in[1];
    const float* Wc1  = (const float*)d_in[2];
    const float* bc1  = (const float*)d_in[3];
    const float* Wc2  = (const float*)d_in[4];
    const float* bc2  = (const float*)d_in[5];
    const float* Wg1  = (const float*)d_in[6];
    const float* bg   = (const float*)d_in[7];
    const float* Wd   = (const float*)d_in[8];
    const float* bd   = (const float*)d_in[9];
    const float* Wo   = (const float*)d_in[10];
    const float* bo   = (const float*)d_in[11];
    float* out = (float*)d_out;

    static bool attr_done = false;
    if (!attr_done) {
        cudaFuncSetAttribute(gemm_kernel,
                             cudaFuncAttributeMaxDynamicSharedMemorySize, GEMM_SMEM);
        attr_done = true;
    }

    fused_prep_cond<<<1024, 256>>>(edges, ts, Wc1, bc1, Wc2, bc2);
    gemm_kernel<<<dim3(BB, NN / MT), 256, GEMM_SMEM>>>(ts, Wg1, bg, Wd, bd,
                                                       Wo, bo, out);
}

// round 8
// speedup vs baseline: 1.5184x; 1.0939x over previous
#include <cuda_runtime.h>
#include <cuda_bf16.h>
#include <math.h>
#include <stdint.h>

// Problem constants
#define NN   4096
#define BB   4
#define DD   4
#define TT   5
#define F1C  32
#define F2C  64
#define CF   256            // BB * F2C columns of cond matrix
#define NSEG (NN / 32)      // 128 u32 words per packed row

// GEMM tiling
#define MT     64
#define NT     64
#define KT     64
#define KSPLIT 2
#define NKT2   (NN / KSPLIT / KT)     // 32 k-tiles per CTA
#define LDSB   144                    // padded smem row stride bytes
#define ATILE  (MT * LDSB)            // 9216
#define BTILE  (NT * LDSB)            // 9216
#define GTILE  (ATILE + BTILE)        // 18432
#define GEMM_SMEM (3 * GTILE)         // 55296
#define EPI_SMEM  (17024 * 4)         // 68096

// Scratch (device globals — no allocation allowed)
__device__ float          g_cond[NN * CF];        // cond fp32 [n][b*64+f]
__device__ __nv_bfloat16  g_condT[CF * NN];       // cond bf16 transposed [c][n]
__device__ __nv_bfloat16  g_A16[(size_t)NN * NN]; // dense bf16 adjacency (32 MB)
__device__ unsigned       g_Abits[NN * NSEG];     // bit-packed adjacency
__device__ float          g_invdeg[NN];
__device__ unsigned       g_colOr[NSEG];          // column-nonzero bitmask
__device__ float          g_Spart[KSPLIT][NN * CF]; // K-split partials (2x4MB)

// ---------------------------------------------------------------------------
// helpers
// ---------------------------------------------------------------------------
__device__ __forceinline__ void cp_async16(void* smem_dst, const void* gmem_src) {
    unsigned saddr = (unsigned)__cvta_generic_to_shared(smem_dst);
    asm volatile("cp.async.cg.shared.global [%0], [%1], 16;\n"
                 :: "r"(saddr), "l"(gmem_src) : "memory");
}
__device__ __forceinline__ void cp_async_commit() {
    asm volatile("cp.async.commit_group;\n" ::: "memory");
}
template <int N>
__device__ __forceinline__ void cp_async_wait() {
    asm volatile("cp.async.wait_group %0;\n" :: "n"(N) : "memory");
}
__device__ __forceinline__ void ldsm_x4(uint32_t &r0, uint32_t &r1,
                                        uint32_t &r2, uint32_t &r3,
                                        uint32_t saddr) {
    asm volatile("ldmatrix.sync.aligned.m8n8.x4.shared.b16 {%0,%1,%2,%3}, [%4];\n"
                 : "=r"(r0), "=r"(r1), "=r"(r2), "=r"(r3) : "r"(saddr));
}
__device__ __forceinline__ void mma_bf16_v(float c[4],
    uint32_t a0, uint32_t a1, uint32_t a2, uint32_t a3,
    uint32_t b0, uint32_t b1)
{
    asm volatile(
        "mma.sync.aligned.m16n8k16.row.col.f32.bf16.bf16.f32 "
        "{%0,%1,%2,%3}, {%4,%5,%6,%7}, {%8,%9}, {%0,%1,%2,%3};\n"
        : "+f"(c[0]), "+f"(c[1]), "+f"(c[2]), "+f"(c[3])
        : "r"(a0), "r"(a1), "r"(a2), "r"(a3), "r"(b0), "r"(b1));
}
__device__ __forceinline__ void fma2(float2 &a, const float2 &x, const float2 &y) {
    unsigned long long &ar = reinterpret_cast<unsigned long long &>(a);
    const unsigned long long &xr = reinterpret_cast<const unsigned long long &>(x);
    const unsigned long long &yr = reinterpret_cast<const unsigned long long &>(y);
    asm("fma.rn.f32x2 %0, %1, %2, %0;" : "+l"(ar) : "l"(xr), "l"(yr));
}

// ---------------------------------------------------------------------------
// Fused kernel 1: CTAs [0,512) = prep, CTAs [512,1024) = temporal conv.
// prep: warp per row; thread-local bit building, coalesced A16/bit stores,
// popc degree, spread smem atomics for colOr.
// ---------------------------------------------------------------------------
struct CondSmem {
    float sW1[3 * DD * F1C];       // 384
    float sW2t[3 * 64 * 36];       // 6912
    float sb1[F1C];
    float sb2[F2C];
    float sx[8][20];
    float sh[8][96];
    __nv_bfloat16 scT[CF][8];
};

__global__ __launch_bounds__(256) void fused_prep_cond(
    const int*   __restrict__ edges,
    const float* __restrict__ ts,
    const float* __restrict__ Wc1, const float* __restrict__ bc1,
    const float* __restrict__ Wc2, const float* __restrict__ bc2)
{
    __shared__ __align__(16) char pool[sizeof(CondSmem)];
    const int tid  = threadIdx.x;
    const int wid  = tid >> 5;
    const int lane = tid & 31;

    if (blockIdx.x < 512) {
        // ---------------- prep: warp per row ----------------
        unsigned* sOr = (unsigned*)pool;   // 128 words
        for (int i = tid; i < NSEG; i += 256) sOr[i] = 0u;
        __syncthreads();

        const int j = blockIdx.x * 8 + wid;
        const int* row = edges + (size_t)j * NN;
        int deg = 0;

        #pragma unroll 1
        for (int it = 0; it < 8; it++) {
            const int k0 = it * 512 + lane * 16;  // 16 consecutive k per thread
            int4 v0 = *(const int4*)(row + k0);
            int4 v1 = *(const int4*)(row + k0 + 4);
            int4 v2 = *(const int4*)(row + k0 + 8);
            int4 v3 = *(const int4*)(row + k0 + 12);
            int e[16] = {v0.x,v0.y,v0.z,v0.w, v1.x,v1.y,v1.z,v1.w,
                         v2.x,v2.y,v2.z,v2.w, v3.x,v3.y,v3.z,v3.w};
            unsigned bits = 0;
            #pragma unroll
            for (int i = 0; i < 16; i++) bits |= (e[i] != 0 ? 1u : 0u) << i;
            deg += __popc(bits);

            // bf16 row: 16 bf16 = 8 u32 (coalesced: thread writes 32B run)
            uint32_t p[8];
            #pragma unroll
            for (int i = 0; i < 8; i++)
                p[i] = ((bits >> (2*i)) & 1u ? 0x3F80u : 0u)
                     | ((bits >> (2*i+1)) & 1u ? 0x3F800000u : 0u);
            uint4* dst = (uint4*)(g_A16 + (size_t)j * NN + k0);
            dst[0] = make_uint4(p[0], p[1], p[2], p[3]);
            dst[1] = make_uint4(p[4], p[5], p[6], p[7]);

            // combine lane pairs -> one u32 bit word per 32 k
            unsigned hi = __shfl_down_sync(0xffffffffu, bits, 1);
            if ((lane & 1) == 0) {
                const unsigned w = bits | (hi << 16);
                const int seg = it * 16 + (lane >> 1);
                g_Abits[(size_t)j * NSEG + seg] = w;
                if (w) atomicOr(&sOr[seg], w);
            }
        }
        // warp reduce degree
        #pragma unroll
        for (int off = 16; off > 0; off >>= 1)
            deg += __shfl_down_sync(0xffffffffu, deg, off);
        if (lane == 0) g_invdeg[j] = 1.0f / fmaxf((float)deg, 1.0f);
        __syncthreads();
        for (int i = tid; i < NSEG; i += 256)
            if (sOr[i]) atomicOr(&g_colOr[i], sOr[i]);
    } else {
        // ---------------- cond ----------------
        CondSmem* cs = (CondSmem*)pool;
        const int n0 = (blockIdx.x - 512) * 8;

        for (int i = tid; i < 3 * F1C * F2C; i += 256) {
            int f = i & 63;
            int pc = i >> 6;
            int p = pc >> 5, c = pc & 31;
            cs->sW2t[(p * 64 + f) * 36 + c] = Wc2[i];
        }
        for (int i = tid; i < 3 * DD * F1C; i += 256) cs->sW1[i] = Wc1[i];
        if (tid < F1C) cs->sb1[tid] = bc1[tid];
        if (tid < F2C) cs->sb2[tid] = bc2[tid];
        __syncthreads();

        for (int it = 0; it < 4; it++) {
            const int item = wid * 4 + it;
            const int b    = item >> 3;
            const int nloc = item & 7;
            const int n    = n0 + nloc;

            if (lane < TT * DD) {
                int t = lane >> 2, d = lane & 3;
                cs->sx[wid][lane] = ts[((size_t)(b * TT + t) * NN + n) * DD + d];
            }
            __syncwarp();

            #pragma unroll
            for (int p = 0; p < 3; p++) {
                float s = cs->sb1[lane];
                #pragma unroll
                for (int r = 0; r < 3; r++)
                    #pragma unroll
                    for (int d = 0; d < DD; d++)
                        s += cs->sx[wid][(p + r) * DD + d]
                           * cs->sW1[(r * DD + d) * F1C + lane];
                cs->sh[wid][p * 32 + lane] = fmaxf(s, 0.f);
            }
            __syncwarp();

            float s0 = cs->sb2[lane], s1 = cs->sb2[lane + 32];
            #pragma unroll
            for (int p = 0; p < 3; p++) {
                const float4* h4 = (const float4*)&cs->sh[wid][p * 32];
                const float4* wa = (const float4*)&cs->sW2t[(p * 64 + lane) * 36];
                const float4* wb = (const float4*)&cs->sW2t[(p * 64 + lane + 32) * 36];
                #pragma unroll
                for (int q = 0; q < 8; q++) {
                    float4 h = h4[q], a = wa[q], bq = wb[q];
                    s0 += h.x * a.x + h.y * a.y + h.z * a.z + h.w * a.w;
                    s1 += h.x * bq.x + h.y * bq.y + h.z * bq.z + h.w * bq.w;
                }
            }
            const int cc0 = b * F2C + lane;
            g_cond[(size_t)n * CF + cc0]      = s0;
            g_cond[(size_t)n * CF + cc0 + 32] = s1;
            cs->scT[cc0][nloc]      = __float2bfloat16(s0);
            cs->scT[cc0 + 32][nloc] = __float2bfloat16(s1);
            __syncwarp();
        }
        __syncthreads();

        if (tid < CF)
            *(int4*)&g_condT[(size_t)tid * NN + n0] = *(int4*)&cs->scT[tid][0];
    }
}

// ---------------------------------------------------------------------------
// Kernel 2: K-split partial GEMM S = A @ cond (bf16 mma.sync).
// grid (4 batches, 64 row-groups, 2 k-splits) x 128 threads.
// CTA: 64 rows x 64 cols x K=2048. Warp tile m32 x n32.
// Pure cp.async + ldmatrix + HMMA mainloop (A pre-expanded to bf16 in prep).
// ---------------------------------------------------------------------------
__global__ __launch_bounds__(128, 4) void gemm_kernel(float* __restrict__ dummy)
{
    extern __shared__ char smem[];
    const unsigned smem_u = (unsigned)__cvta_generic_to_shared(smem);

    const int tid  = threadIdx.x;
    const int wid  = tid >> 5;
    const int lane = tid & 31;
    const int g    = lane >> 2;
    const int t    = lane & 3;
    const int mi2  = wid >> 1;            // 0..1 m32 block
    const int nj2  = wid & 1;             // 0..1 n32 block
    const int cb   = blockIdx.x * NT;     // batch * 64 (condT row base)
    const int j0   = blockIdx.y * MT;
    const int z    = blockIdx.z;
    const int ks0  = z * (NN / KSPLIT);

    const int aoff = (mi2 * 32 + ((lane >> 3) & 1) * 8 + (lane & 7)) * LDSB
                   + (lane >> 4) * 16;
    const int boff = (nj2 * 32 + (lane >> 4) * 8 + (lane & 7)) * LDSB
                   + ((lane >> 3) & 1) * 16;

    float acc[2][4][4] = {};

    // stage loader: A tile + B tile, one commit group per stage
    auto load_stage = [&](int slot, int kt_abs) {
        char* base = smem + slot * GTILE;
        const int k = ks0 + kt_abs * KT;
        for (int ch = tid; ch < MT * 8; ch += 128) {
            int rw = ch >> 3, off = ch & 7;
            cp_async16(base + rw * LDSB + off * 16,
                       g_A16 + (size_t)(j0 + rw) * NN + k + off * 8);
        }
        for (int ch = tid; ch < NT * 8; ch += 128) {
            int rw = ch >> 3, off = ch & 7;
            cp_async16(base + ATILE + rw * LDSB + off * 16,
                       g_condT + (size_t)(cb + rw) * NN + k + off * 8);
        }
        cp_async_commit();
    };

    load_stage(0, 0);
    load_stage(1, 1);
    cp_async_wait<1>();
    __syncthreads();

    #pragma unroll 1
    for (int kt = 0; kt < NKT2; kt++) {
        if (kt + 2 < NKT2) load_stage((kt + 2) % 3, kt + 2);

        const unsigned Au = smem_u + (kt % 3) * GTILE;
        const unsigned Bu = Au + ATILE;

        #pragma unroll
        for (int kk = 0; kk < 4; kk++) {
            const int kb = kk * 32;
            uint32_t a0[4], a1[4], b0[4], b1[4];
            ldsm_x4(a0[0], a0[1], a0[2], a0[3], Au + aoff + kb);
            ldsm_x4(a1[0], a1[1], a1[2], a1[3], Au + aoff + 16 * LDSB + kb);
            ldsm_x4(b0[0], b0[1], b0[2], b0[3], Bu + boff + kb);
            ldsm_x4(b1[0], b1[1], b1[2], b1[3], Bu + boff + 16 * LDSB + kb);
            #pragma unroll
            for (int h = 0; h < 2; h++) {
                uint32_t* a = h ? a1 : a0;
                mma_bf16_v(acc[h][0], a[0], a[1], a[2], a[3], b0[0], b0[1]);
                mma_bf16_v(acc[h][1], a[0], a[1], a[2], a[3], b0[2], b0[3]);
                mma_bf16_v(acc[h][2], a[0], a[1], a[2], a[3], b1[0], b1[1]);
                mma_bf16_v(acc[h][3], a[0], a[1], a[2], a[3], b1[2], b1[3]);
            }
        }
        if (kt + 2 < NKT2) cp_async_wait<1>(); else cp_async_wait<0>();
        __syncthreads();
    }

    // store partials
    float* Sp = g_Spart[z];
    #pragma unroll
    for (int h = 0; h < 2; h++) {
        const int r = mi2 * 32 + h * 16 + g;
        #pragma unroll
        for (int ni = 0; ni < 4; ni++) {
            const int col = cb + nj2 * 32 + ni * 8 + 2 * t;
            *(float2*)&Sp[(size_t)(j0 + r) * CF + col] =
                make_float2(acc[h][ni][0], acc[h][ni][1]);
            *(float2*)&Sp[(size_t)(j0 + r + 8) * CF + col] =
                make_float2(acc[h][ni][2], acc[h][ni][3]);
        }
    }
}

// ---------------------------------------------------------------------------
// Kernel 3: epilogue — combine K-split partials + GEMV chain.
// grid (4, 64) x 256 threads; natural [r][c] smem layouts (conflict-free).
// ---------------------------------------------------------------------------
__global__ __launch_bounds__(256) void epi_kernel(
    const float* __restrict__ ts,
    const float* __restrict__ Wg1, const float* __restrict__ bg,
    const float* __restrict__ Wd,  const float* __restrict__ bd,
    const float* __restrict__ Wo,  const float* __restrict__ bo,
    float* __restrict__ out)
{
    extern __shared__ float sm[];
    float* agg  = sm;            // [r][c] 4096 -> later G
    float* cnd  = sm + 4096;     // [r][c] 4096 -> later H
    float* sW   = sm + 8192;     // 8192: Wg1 then Wd
    float* sWo  = sm + 16384;    // 256
    float* sbg  = sm + 16640;
    float* sbd  = sm + 16704;
    float* sbo  = sm + 16768;
    float* sinv = sm + 16832;
    float* sal  = sm + 16896;
    float* sdg  = sm + 16960;

    const int tid = threadIdx.x;
    const int b   = blockIdx.x;
    const int j0  = blockIdx.y * 64;
    const int cb  = b * 64;

    if (tid < 64) {
        const int j = j0 + tid;
        sinv[tid] = g_invdeg[j];
        unsigned dw = g_Abits[(size_t)j * NSEG + (j >> 5)];
        sdg[tid] = ((dw >> (j & 31)) & 1u) ? 1.f : 0.f;
        unsigned aw = g_colOr[j >> 5];
        sal[tid] = ((aw >> (j & 31)) & 1u) ? 1.f : 0.f;
    }
    for (int i = tid; i < 4096; i += 256) sW[i] = Wg1[i];
    if (tid < 256) sWo[tid] = Wo[tid];
    if (tid < 64) { sbg[tid] = bg[tid]; sbd[tid] = bd[tid]; }
    if (tid < 4)  sbo[tid] = bo[tid];
    __syncthreads();

    // load S partials + transform
    for (int idx = tid; idx < 4096; idx += 256) {
        const int r = idx >> 6, c = idx & 63;
        const size_t gix = (size_t)(j0 + r) * CF + cb + c;
        const float cv = g_cond[gix];
        const float s  = g_Spart[0][gix] + g_Spart[1][gix];
        cnd[r * 64 + c] = cv;
        agg[r * 64 + c] = (s - sdg[r] * cv) * sinv[r];
    }
    __syncthreads();

    const int fq = tid & 15, rq = tid >> 4;
    const int f0 = fq * 4, r0 = rq * 4;

    // ---- stage 1: G = tanh(agg @ Wg1 + bg) * alive ----
    float2 ac[4][2] = {};
    #pragma unroll 4
    for (int i = 0; i < 64; i++) {
        float4 wv = *(const float4*)&sW[i * 64 + f0];
        float2 w0 = make_float2(wv.x, wv.y), w1 = make_float2(wv.z, wv.w);
        float a0 = agg[(r0 + 0) * 64 + i];
        float a1 = agg[(r0 + 1) * 64 + i];
        float a2 = agg[(r0 + 2) * 64 + i];
        float a3 = agg[(r0 + 3) * 64 + i];
        float2 d0 = make_float2(a0, a0), d1 = make_float2(a1, a1);
        float2 d2 = make_float2(a2, a2), d3 = make_float2(a3, a3);
        fma2(ac[0][0], d0, w0); fma2(ac[0][1], d0, w1);
        fma2(ac[1][0], d1, w0); fma2(ac[1][1], d1, w1);
        fma2(ac[2][0], d2, w0); fma2(ac[2][1], d2, w1);
        fma2(ac[3][0], d3, w0); fma2(ac[3][1], d3, w1);
    }
    float Gv[4][4];
    #pragma unroll
    for (int ri = 0; ri < 4; ri++) {
        const float al = sal[r0 + ri];
        Gv[ri][0] = tanhf(ac[ri][0].x + sbg[f0 + 0]) * al;
        Gv[ri][1] = tanhf(ac[ri][0].y + sbg[f0 + 1]) * al;
        Gv[ri][2] = tanhf(ac[ri][1].x + sbg[f0 + 2]) * al;
        Gv[ri][3] = tanhf(ac[ri][1].y + sbg[f0 + 3]) * al;
    }
    __syncthreads();
    #pragma unroll
    for (int ri = 0; ri < 4; ri++)
        *(float4*)&agg[(r0 + ri) * 64 + f0] =
            make_float4(Gv[ri][0], Gv[ri][1], Gv[ri][2], Gv[ri][3]);
    for (int i = tid; i < 8192; i += 256) sW[i] = Wd[i];
    __syncthreads();

    // ---- stage 2: H = relu([cond, G] @ Wd + bd) ----
    float2 hc[4][2] = {};
    #pragma unroll 4
    for (int i = 0; i < 64; i++) {
        float4 wv = *(const float4*)&sW[i * 64 + f0];
        float2 w0 = make_float2(wv.x, wv.y), w1 = make_float2(wv.z, wv.w);
        float c0v = cnd[(r0 + 0) * 64 + i];
        float c1v = cnd[(r0 + 1) * 64 + i];
        float c2v = cnd[(r0 + 2) * 64 + i];
        float c3v = cnd[(r0 + 3) * 64 + i];
        float2 d0 = make_float2(c0v, c0v), d1 = make_float2(c1v, c1v);
        float2 d2 = make_float2(c2v, c2v), d3 = make_float2(c3v, c3v);
        fma2(hc[0][0], d0, w0); fma2(hc[0][1], d0, w1);
        fma2(hc[1][0], d1, w0); fma2(hc[1][1], d1, w1);
        fma2(hc[2][0], d2, w0); fma2(hc[2][1], d2, w1);
        fma2(hc[3][0], d3, w0); fma2(hc[3][1], d3, w1);
    }
    #pragma unroll 4
    for (int i = 0; i < 64; i++) {
        float4 wv = *(const float4*)&sW[(64 + i) * 64 + f0];
        float2 w0 = make_float2(wv.x, wv.y), w1 = make_float2(wv.z, wv.w);
        float g0 = agg[(r0 + 0) * 64 + i];
        float g1 = agg[(r0 + 1) * 64 + i];
        float g2 = agg[(r0 + 2) * 64 + i];
        float g3 = agg[(r0 + 3) * 64 + i];
        float2 d0 = make_float2(g0, g0), d1 = make_float2(g1, g1);
        float2 d2 = make_float2(g2, g2), d3 = make_float2(g3, g3);
        fma2(hc[0][0], d0, w0); fma2(hc[0][1], d0, w1);
        fma2(hc[1][0], d1, w0); fma2(hc[1][1], d1, w1);
        fma2(hc[2][0], d2, w0); fma2(hc[2][1], d2, w1);
        fma2(hc[3][0], d3, w0); fma2(hc[3][1], d3, w1);
    }
    float Hv[4][4];
    #pragma unroll
    for (int ri = 0; ri < 4; ri++) {
        Hv[ri][0] = fmaxf(hc[ri][0].x + sbd[f0 + 0], 0.f);
        Hv[ri][1] = fmaxf(hc[ri][0].y + sbd[f0 + 1], 0.f);
        Hv[ri][2] = fmaxf(hc[ri][1].x + sbd[f0 + 2], 0.f);
        Hv[ri][3] = fmaxf(hc[ri][1].y + sbd[f0 + 3], 0.f);
    }
    __syncthreads();
    #pragma unroll
    for (int ri = 0; ri < 4; ri++)
        *(float4*)&cnd[(r0 + ri) * 64 + f0] =
            make_float4(Hv[ri][0], Hv[ri][1], Hv[ri][2], Hv[ri][3]);
    __syncthreads();

    // ---- stage 3: out = last + tanh(H @ Wo + bo) ----
    {
        const int r = tid >> 2, d = tid & 3;
        const int j = j0 + r;
        float o = sbo[d];
        #pragma unroll
        for (int f = 0; f < 64; f++) o += cnd[r * 64 + f] * sWo[f * DD + d];
        const float last = ts[((size_t)(b * TT + 4) * NN + j) * DD + d];
        out[((size_t)b * NN + j) * DD + d] = last + tanhf(o);
    }
}

// ---------------------------------------------------------------------------
// Inputs (metadata order): time_segs, edges, Wc1, bc1, Wc2, bc2,
//                          Wg1, bg, Wd, bd, Wo, bo
// ---------------------------------------------------------------------------
extern "C" void kernel_launch(void* const* d_in, const int* in_sizes, int n_in,
                              void* d_out, int out_size)
{
    const float* ts   = (const float*)d_in[0];
    const int*   edges= (const int*)  d_in[1];
    const float* Wc1  = (const float*)d_in[2];
    const float* bc1  = (const float*)d_in[3];
    const float* Wc2  = (const float*)d_in[4];
    const float* bc2  = (const float*)d_in[5];
    const float* Wg1  = (const float*)d_in[6];
    const float* bg   = (const float*)d_in[7];
    const float* Wd   = (const float*)d_in[8];
    const float* bd   = (const float*)d_in[9];
    const float* Wo   = (const float*)d_in[10];
    const float* bo   = (const float*)d_in[11];
    float* out = (float*)d_out;

    static bool attr_done = false;
    if (!attr_done) {
        cudaFuncSetAttribute(gemm_kernel,
                             cudaFuncAttributeMaxDynamicSharedMemorySize, GEMM_SMEM);
        cudaFuncSetAttribute(epi_kernel,
                             cudaFuncAttributeMaxDynamicSharedMemorySize, EPI_SMEM);
        attr_done = true;
    }

    fused_prep_cond<<<1024, 256>>>(edges, ts, Wc1, bc1, Wc2, bc2);
    gemm_kernel<<<dim3(BB, NN / MT, KSPLIT), 128, GEMM_SMEM>>>(out);
    epi_kernel<<<dim3(BB, NN / 64), 256, EPI_SMEM>>>(ts, Wg1, bg, Wd, bd,
                                                     Wo, bo, out);
}